// round 17
// baseline (speedup 1.0000x reference)
#include <cuda_runtime.h>

#define NPTS   8192
#define BATCH  4
#define TPB    128
#define QTY    8                 // ty groups (query dim)
#define QPT    8                 // queries per thread per pass
#define QB     (QTY*QPT)         // 64 queries per pass
#define QI     2                 // query passes per block
#define QBB    (QB*QI)           // 128 queries per block
#define NQT    (NPTS/QBB)        // 64 query tiles
#define TTX    16                // tx groups (target dim)
#define TPP    32                // packed target-pairs per thread (64 targets)
#define TB     (TTX*TPP*2)       // 1024 targets per block
#define NTT    (NPTS/TB)         // 8 target tiles
#define NPAIR  (TB/2)            // 512 target pairs per block
#define NCOPY  (QTY/2)           // 4 sRed copies (warp-folded via shfl)
#define QSTR   (QB+1)            // padded stride for q-dir smem reduce (65)
#define NBLK2  256
#define POSINF 0x7F800000

// Global min accumulators: u >= 0 so int-punned atomicMin == exact float min.
__device__ int   g_qmin[BATCH][NPTS];   // pred-side min-u (128KB, L2-resident)
__device__ int   g_tmin[BATCH][NPTS];   // targ-side min-u (128KB, L2-resident)
__device__ float g_partials[NBLK2];
__device__ int   g_counter;             // last-block ticket (reset each run)

__device__ __forceinline__ unsigned long long ffma2(unsigned long long a,
                                                    unsigned long long b,
                                                    unsigned long long c) {
    unsigned long long d;
    asm("fma.rn.f32x2 %0, %1, %2, %3;" : "=l"(d) : "l"(a), "l"(b), "l"(c));
    return d;
}
__device__ __forceinline__ unsigned long long add2(unsigned long long a,
                                                   unsigned long long b) {
    unsigned long long d;
    asm("add.rn.f32x2 %0, %1, %2;" : "=l"(d) : "l"(a), "l"(b));
    return d;
}
__device__ __forceinline__ unsigned long long pack2(float lo, float hi) {
    unsigned long long r;
    asm("mov.b64 %0, {%1, %2};" : "=l"(r) : "f"(lo), "f"(hi));
    return r;
}
__device__ __forceinline__ float2 unpack2(unsigned long long v) {
    float2 r;
    asm("mov.b64 {%0, %1}, %2;" : "=f"(r.x), "=f"(r.y) : "l"(v));
    return r;
}
__device__ __forceinline__ void atomic_min_pos(int* addr, float v) {
    atomicMin(addr, __float_as_int(fmaxf(v, 0.f)));   // exact for v >= 0
}

// Reset the min accumulators to +inf (runs first every launch).
// 32 blocks x 1024 threads = 32768 = BATCH*NPTS entries; each thread
// initializes exactly one in-bounds element of EACH array (no overrun).
__global__ void chamfer_init(void) {
    const int i = blockIdx.x * 1024 + threadIdx.x;    // 0..32767
    (&g_qmin[0][0])[i] = POSINF;
    (&g_tmin[0][0])[i] = POSINF;
}

// Block = (query-tile of 128 via 2 passes of 64, target-tile of 1024, batch).
// u = 0.5*d^2 = g + h - p.t per pair (2 targets per f32x2).
//   min over targets -> g_qmin (atomicMin); min over queries -> g_tmin.
__global__ __launch_bounds__(TPB, 6)
void chamfer_pair_kernel(const float* __restrict__ pred,
                         const float* __restrict__ targ) {
    __shared__ float4 sA[NPAIR];   // (x0,x1, y0,y1) per target pair   8KB
    __shared__ float4 sB[NPAIR];   // (z0,z1, h0,h1)                   8KB
    __shared__ unsigned long long sRed[NCOPY * NPAIR];   // 16KB t-side buffer
    __shared__ float sQ[TTX * QSTR];                     // 4.2KB q-side buffer

    const int tid = threadIdx.x;
    const int tx  = tid & 15;
    const int ty  = tid >> 4;
    const int wid = tid >> 5;     // warp id = ty>>1
    const int qt  = blockIdx.x;   // 0..63
    const int tt  = blockIdx.y;   // 0..7
    const int b   = blockIdx.z;   // 0..3

    const float* P = pred + b * 3 * NPTS;
    const float* T = targ + b * 3 * NPTS;

    // ---- stage this tile's 1024 targets (two float4-groups per thread) ----
    {
        const float* Tx = T + tt * TB;
        const float* Ty = Tx + NPTS;
        const float* Tz = Tx + 2 * NPTS;
#pragma unroll
        for (int i = 0; i < 2; i++) {
            const int g4 = tid + i * TPB;       // float4-group 0..255
            const int m  = g4 * 4;
            const float4 x4 = *reinterpret_cast<const float4*>(Tx + m);
            const float4 y4 = *reinterpret_cast<const float4*>(Ty + m);
            const float4 z4 = *reinterpret_cast<const float4*>(Tz + m);
            const float h0 = 0.5f * (x4.x * x4.x + y4.x * y4.x + z4.x * z4.x);
            const float h1 = 0.5f * (x4.y * x4.y + y4.y * y4.y + z4.y * z4.y);
            const float h2 = 0.5f * (x4.z * x4.z + y4.z * y4.z + z4.z * z4.z);
            const float h3 = 0.5f * (x4.w * x4.w + y4.w * y4.w + z4.w * z4.w);
            sA[2 * g4]     = make_float4(x4.x, x4.y, y4.x, y4.y);
            sB[2 * g4]     = make_float4(z4.x, z4.y, h0, h1);
            sA[2 * g4 + 1] = make_float4(x4.z, x4.w, y4.z, y4.w);
            sB[2 * g4 + 1] = make_float4(z4.z, z4.w, h2, h3);
        }
    }
    __syncthreads();

    const ulonglong2* A  = reinterpret_cast<const ulonglong2*>(sA);
    const ulonglong2* Bq = reinterpret_cast<const ulonglong2*>(sB);

    for (int qi = 0; qi < QI; qi++) {
        // ---- load this pass's 8 register queries (lane-duplicated packs) ----
        unsigned long long npx[QPT], npy[QPT], npz[QPT], gpk[QPT];
        float accl[QPT], acch[QPT];
#pragma unroll
        for (int q = 0; q < QPT; q++) {
            const int idx = qt * QBB + qi * QB + ty * QPT + q;
            const float x = P[idx];
            const float y = P[NPTS + idx];
            const float z = P[2 * NPTS + idx];
            npx[q] = pack2(-x, -x);
            npy[q] = pack2(-y, -y);
            npz[q] = pack2(-z, -z);
            const float g = 0.5f * (x * x + y * y + z * z);
            gpk[q] = pack2(g, g);
            accl[q] = 1e30f;
            acch[q] = 1e30f;
        }

#pragma unroll 8
        for (int jj = 0; jj < TPP; ++jj) {
            const int j = jj * TTX + tx;   // lane-consecutive: conflict-free
            const ulonglong2 av = A[j];    // (x0,x1), (y0,y1)
            const ulonglong2 bv = Bq[j];   // (z0,z1), (h0,h1)
            float tl0, tl1, th0, th1;      // 4 running t-side chains
#pragma unroll
            for (int q = 0; q < QPT; q++) {
                unsigned long long u = ffma2(npx[q], av.x, bv.y);  // h - x.tx
                u = ffma2(npy[q], av.y, u);
                u = ffma2(npz[q], bv.x, u);
                u = add2(gpk[q], u);            // u = g + h - p.t = d^2/2
                const float2 uf = unpack2(u);
                accl[q] = fminf(accl[q], uf.x); // pred side (per query)
                acch[q] = fminf(acch[q], uf.y);
                if (q == 0)      { tl0 = uf.x; th0 = uf.y; }
                else if (q == 1) { tl1 = uf.x; th1 = uf.y; }
                else if (q & 1)  { tl1 = fminf(tl1, uf.x); th1 = fminf(th1, uf.y); }
                else             { tl0 = fminf(tl0, uf.x); th0 = fminf(th0, uf.y); }
            }
            float tl = fminf(tl0, tl1);
            float th = fminf(th0, th1);
            // fold the two half-warps (ty = 2w, 2w+1) before storing
            tl = fminf(tl, __shfl_xor_sync(0xFFFFFFFFu, tl, 16));
            th = fminf(th, __shfl_xor_sync(0xFFFFFFFFu, th, 16));
            if ((ty & 1) == 0) {
                if (qi == 0) {
                    sRed[wid * NPAIR + j] = pack2(tl, th);
                } else {      // same thread owns this slot: safe read-min-write
                    const float2 o = unpack2(sRed[wid * NPAIR + j]);
                    sRed[wid * NPAIR + j] =
                        pack2(fminf(tl, o.x), fminf(th, o.y));
                }
            }
        }

        // ---- q-direction for this pass: fold lo/hi, min over 16 tx ----
#pragma unroll
        for (int q = 0; q < QPT; q++)
            sQ[tx * QSTR + ty * QPT + q] = fminf(accl[q], acch[q]);
        __syncthreads();
        if (tid < QB) {
            float m = sQ[tid];
#pragma unroll
            for (int t2 = 1; t2 < TTX; t2++) m = fminf(m, sQ[t2 * QSTR + tid]);
            atomic_min_pos(&g_qmin[b][qt * QBB + qi * QB + tid], m);
        }
        __syncthreads();   // protect sQ (and order sRed) before next pass
    }

    // ---- t-direction: min over the 4 warp copies, atomicMin 1024 values ----
#pragma unroll
    for (int oo = 0; oo < 4; oo++) {
        const int o = oo * TPB + tid;      // pair index 0..511, lanes consecutive
        float2 m = unpack2(sRed[o]);
#pragma unroll
        for (int t2 = 1; t2 < NCOPY; t2++) {
            const float2 v = unpack2(sRed[t2 * NPAIR + o]);
            m.x = fminf(m.x, v.x);
            m.y = fminf(m.y, v.y);
        }
        atomic_min_pos(&g_tmin[b][tt * TB + 2 * o],     m.x);
        atomic_min_pos(&g_tmin[b][tt * TB + 2 * o + 1], m.y);
    }
}

// Fused combine + final reduce: one load per thread, sqrt, deterministic sums,
// last-block finalize.
__global__ __launch_bounds__(256)
void chamfer_combine(float* __restrict__ out) {
    __shared__ float red[8];
    __shared__ int sLast;
    const int tid = threadIdx.x;
    const int gp  = blockIdx.x * 256 + tid;   // 0..65535

    const float u = (gp < BATCH * NPTS)
        ? __int_as_float((&g_qmin[0][0])[gp])
        : __int_as_float((&g_tmin[0][0])[gp - BATCH * NPTS]);

    float d = sqrtf(2.f * u);                 // u >= 0 (clamped at atomic site)
#pragma unroll
    for (int off = 16; off > 0; off >>= 1)
        d += __shfl_down_sync(0xFFFFFFFFu, d, off);
    if ((tid & 31) == 0) red[tid >> 5] = d;
    __syncthreads();
    if (tid == 0) {
        float t = 0.f;
#pragma unroll
        for (int w = 0; w < 8; w++) t += red[w];
        g_partials[blockIdx.x] = t;
        __threadfence();
        sLast = (atomicAdd(&g_counter, 1) == NBLK2 - 1);
    }
    __syncthreads();

    if (sLast) {                              // exactly one block finalizes
        __threadfence();
        float v = g_partials[tid];            // fixed-order deterministic sum
#pragma unroll
        for (int off = 16; off > 0; off >>= 1)
            v += __shfl_down_sync(0xFFFFFFFFu, v, off);
        if ((tid & 31) == 0) red[tid >> 5] = v;
        __syncthreads();
        if (tid == 0) {
            float s = 0.f;
#pragma unroll
            for (int w = 0; w < 8; w++) s += red[w];
            out[0] = s * (1.0f / (BATCH * NPTS));
            g_counter = 0;                    // reset for next graph replay
        }
    }
}

extern "C" void kernel_launch(void* const* d_in, const int* in_sizes, int n_in,
                              void* d_out, int out_size) {
    const float* pred = (const float*)d_in[0];
    const float* targ = (const float*)d_in[1];
    float* out = (float*)d_out;

    chamfer_init<<<32, 1024>>>();
    dim3 grid(NQT, NTT, BATCH);   // 64 x 8 x 4 = 2048 blocks
    chamfer_pair_kernel<<<grid, TPB>>>(pred, targ);
    chamfer_combine<<<NBLK2, 256>>>(out);
}